// round 13
// baseline (speedup 1.0000x reference)
#include <cuda_runtime.h>

#define W 768
#define H 768
#define HW 589824

// Dynamic shared memory layout for conv_kernel (bytes):
//   Pc    @ 0      : 129*64*4 = 33024   (inclusive column prefix of C)
//   Ps    @ 33024  : 64*129*4 = 33024   (inclusive row prefix of S)
//   segC4 @ 66048  : 16*16*16 = 4096    (per-segment C column sums, float4)
#define CONV_SMEM_BYTES 70144
#define PS_OFF   (33024 / 4)
#define SEG_OFF  (66048 / 16)

// ---------------------------------------------------------------------------
// Kernel A: multi-scale directional response via tile prefix sums.
// (byte-identical to R9 — measured at ~90% of its LDS-crossbar floor)
// ---------------------------------------------------------------------------
__global__ __launch_bounds__(256, 3) void conv_kernel(
    const float* __restrict__ Cg, const float* __restrict__ Sg,
    float* __restrict__ out)
{
    extern __shared__ float smem[];
    float* Pc = smem;                          // [129 * 64]
    float* Ps = smem + PS_OFF;                 // [64 * 129]
    float4* segC4 = (float4*)smem + SEG_OFF;   // [16 * 16]

    const int tid = threadIdx.x;
    const int b  = blockIdx.z;
    const int x0 = blockIdx.x * 64;
    const int y0 = blockIdx.y * 64;
    const float* Cb = Cg + (size_t)b * HW;
    const float* Sb = Sg + (size_t)b * HW;

    const int q  = tid & 15;            // quad-column (cols q*4 .. q*4+3)
    const int sg = tid >> 4;            // 0..15, 8 C-rows each

    // ---- C halo load (rows y0-32 .. y0+95): within-segment prefix held in
    //      registers; only the segment sum hits smem before the sync.
    float4 cpre[8];
    {
        float4 s = make_float4(0.f, 0.f, 0.f, 0.f);
        if (blockIdx.y >= 1 && blockIdx.y <= 10) {       // interior rows
            const float* src = Cb + (y0 - 32 + sg * 8) * W + x0 + q * 4;
            #pragma unroll
            for (int jj = 0; jj < 8; jj++) {
                const float4 v = *(const float4*)(src + jj * W);
                s.x += v.x; s.y += v.y; s.z += v.z; s.w += v.w;
                cpre[jj] = s;
            }
        } else {
            #pragma unroll
            for (int jj = 0; jj < 8; jj++) {
                const int gy = y0 - 32 + sg * 8 + jj;
                float4 v = make_float4(0.f, 0.f, 0.f, 0.f);
                if (gy >= 0 && gy < H)
                    v = *(const float4*)(Cb + gy * W + x0 + q * 4);
                s.x += v.x; s.y += v.y; s.z += v.z; s.w += v.w;
                cpre[jj] = s;
            }
        }
        segC4[sg * 16 + q] = s;
    }

    // ---- S prefix: warp shuffle scan, one warp per row, 8 rows per warp.
    {
        const int l = tid & 31, wp = tid >> 5;
        const int gx0 = x0 - 32 + l * 4;                 // quad-aligned
        const bool intx = (blockIdx.x >= 1) & (blockIdx.x <= 10);
        const bool okx = intx | ((gx0 >= 0) & (gx0 < W)); // all-in or all-out
        #pragma unroll
        for (int rr = 0; rr < 8; rr++) {
            const int row = rr * 8 + wp;
            float4 v = make_float4(0.f, 0.f, 0.f, 0.f);
            if (okx) v = *(const float4*)(Sb + (y0 + row) * W + gx0);
            const float p0 = v.x, p1 = p0 + v.y, p2 = p1 + v.z, p3 = p2 + v.w;
            float t = p3;
            #pragma unroll
            for (int d = 1; d < 32; d <<= 1) {
                const float u = __shfl_up_sync(0xffffffffu, t, d);
                if (l >= d) t += u;
            }
            const float base = t - p3;                   // exclusive base
            float* pr = Ps + row * 129;
            if (l == 0) pr[0] = 0.0f;
            pr[1 + l * 4 + 0] = base + p0;
            pr[1 + l * 4 + 1] = base + p1;
            pr[1 + l * 4 + 2] = base + p2;
            pr[1 + l * 4 + 3] = base + p3;
        }
    }
    __syncthreads();

    // ---- exclusive scan of segC4 in place: 64 threads, conflict-free.
    if (tid < 64) {
        float* arr = (float*)segC4;
        float run = 0.0f;
        #pragma unroll
        for (int s2 = 0; s2 < 16; s2++) {
            const float v = arr[s2 * 64 + tid];
            arr[s2 * 64 + tid] = run;
            run += v;
        }
    }
    __syncthreads();

    // ---- C: add exclusive segment base (single LDS.128), single store pass
    {
        const float4 base = segC4[sg * 16 + q];
        float* dst = Pc + (sg * 8 + 1) * 64 + q * 4;
        #pragma unroll
        for (int jj = 0; jj < 8; jj++) {
            float4 p = cpre[jj];
            p.x += base.x; p.y += base.y; p.z += base.z; p.w += base.w;
            *(float4*)(dst + jj * 64) = p;
        }
        if (tid < 16)
            *(float4*)(Pc + tid * 4) = make_float4(0.f, 0.f, 0.f, 0.f);
    }
    __syncthreads();

    // ---- compute: thread = (col tx, 16 consecutive rows)
    const int tx = tid & 63;
    const int tg = tid >> 6;
    const int XK[7] = {1, 4, 7, 10, 15, 25, 32};
    const float IW[7] = {0.5f, 0.125f, 1.0f / 14.0f, 0.05f,
                         1.0f / 30.0f, 0.02f, 1.0f / 64.0f};
    const float* pc = Pc + tx;
    const int wi = tx + 32;
    float* ob = out + (size_t)b * HW + (y0 + tg * 16) * W + (x0 + tx);

    #pragma unroll
    for (int i = 0; i < 16; i++) {
        const int h = tg * 16 + i + 32;
        const float* psrow = Ps + (tg * 16 + i) * 129;
        const float base = pc[h * 64] + pc[(h + 1) * 64]
                         + psrow[wi] + psrow[wi + 1];
        float r = -3.0e38f;
        #pragma unroll
        for (int k = 0; k < 7; k++) {
            const float t = base
                          - pc[(h - XK[k]) * 64]
                          - pc[(h + XK[k] + 1) * 64]
                          - psrow[wi - XK[k]]
                          - psrow[wi + XK[k] + 1];
            r = fmaxf(r, t * IW[k]);
        }
        ob[i * W] = r;
    }
}

// ---------------------------------------------------------------------------
// Kernel B: pos = relu(resp); 11x11 max pool (separable in-place register
// max pyramid); mask = (pos==pooled && pos>0.5).
// Tile 64(x) x 32(y), 256 threads, launch_bounds(256,6) -> 24.5KB smem,
// 6 blocks = 48 warps/SM, 2304 blocks.
// FIX vs R10: the halo load now iterates a flat strided loop over ALL
// 20x42=840 quad-loads (R10's fixed c4/rg mapping needed 260 slots from
// 256 threads, leaving pos rows {12,25,38} x cols 64..79 uninitialized).
// ---------------------------------------------------------------------------
__global__ __launch_bounds__(256, 6) void pool_kernel(
    const float* __restrict__ resp, float* __restrict__ maskout)
{
    __shared__ float pos[42 * 81];   // rows y0-5..y0+36, cols x0-8..x0+71
    __shared__ float hm[42 * 65];

    const int tid = threadIdx.x;
    const int b  = blockIdx.z;
    const int x0 = blockIdx.x * 64;
    const int y0 = blockIdx.y * 32;
    const float* rb = resp + (size_t)b * HW;

    // ---- halo load: flat strided loop over 840 quad-loads (20 quads x 42 rows)
    {
        const bool interior = (blockIdx.x >= 1) & (blockIdx.x <= 10) &
                              (blockIdx.y >= 1) & (blockIdx.y <= 22);
        if (interior) {
            const float* src = rb + (y0 - 5) * W + (x0 - 8);
            #pragma unroll
            for (int it = 0; it < 4; it++) {
                const int idx = tid + it * 256;
                if (idx < 840) {
                    const int r  = idx / 20;       // const divisor -> mul-shift
                    const int c4 = idx - r * 20;
                    const float4 v = *(const float4*)(src + r * W + c4 * 4);
                    float* dst = pos + r * 81 + c4 * 4;
                    dst[0] = fmaxf(v.x, 0.f);
                    dst[1] = fmaxf(v.y, 0.f);
                    dst[2] = fmaxf(v.z, 0.f);
                    dst[3] = fmaxf(v.w, 0.f);
                }
            }
        } else {
            #pragma unroll
            for (int it = 0; it < 4; it++) {
                const int idx = tid + it * 256;
                if (idx < 840) {
                    const int r  = idx / 20;
                    const int c4 = idx - r * 20;
                    const int gy  = y0 - 5 + r;
                    const int gx0 = x0 - 8 + c4 * 4;   // f4-aligned
                    float4 v = make_float4(0.f, 0.f, 0.f, 0.f);
                    if ((gx0 >= 0) & (gx0 < W) & (gy >= 0) & (gy < H))
                        v = *(const float4*)(rb + gy * W + gx0);
                    float* dst = pos + r * 81 + c4 * 4;
                    dst[0] = fmaxf(v.x, 0.f);
                    dst[1] = fmaxf(v.y, 0.f);
                    dst[2] = fmaxf(v.z, 0.f);
                    dst[3] = fmaxf(v.w, 0.f);
                }
            }
        }
    }
    __syncthreads();

    // ---- horizontal 11-max: 42 rows x 4 segments of 16 outputs.
    // output col c (0..63) window = pos cols c+3 .. c+13.
    if (tid < 168) {
        const int seg = (tid >= 126) ? 3 : (tid >= 84) ? 2 : (tid >= 42) ? 1 : 0;
        const int r   = tid - seg * 42;
        const int c0  = seg * 16;
        const float* src = pos + r * 81 + c0 + 3;
        float p[26];
        #pragma unroll
        for (int i = 0; i < 26; i++) p[i] = src[i];
        #pragma unroll
        for (int i = 0; i < 25; i++) p[i] = fmaxf(p[i], p[i + 1]);
        #pragma unroll
        for (int i = 0; i < 23; i++) p[i] = fmaxf(p[i], p[i + 2]);
        #pragma unroll
        for (int i = 0; i < 19; i++) p[i] = fmaxf(p[i], p[i + 4]);
        float* hr = hm + r * 65 + c0;
        #pragma unroll
        for (int i = 0; i < 16; i++) hr[i] = fmaxf(p[i], p[i + 3]);
    }
    __syncthreads();

    // ---- vertical 11-max + mask: 64 cols x 4 segments of 8 output rows.
    // 18-value window per segment; all 256 threads active.
    {
        const int tx = tid & 63;
        const int r0 = (tid >> 6) * 8;     // 0, 8, 16, 24
        float p[18];
        #pragma unroll
        for (int i = 0; i < 18; i++) p[i] = hm[(r0 + i) * 65 + tx];
        #pragma unroll
        for (int i = 0; i < 17; i++) p[i] = fmaxf(p[i], p[i + 1]);
        #pragma unroll
        for (int i = 0; i < 15; i++) p[i] = fmaxf(p[i], p[i + 2]);
        #pragma unroll
        for (int i = 0; i < 11; i++) p[i] = fmaxf(p[i], p[i + 4]);
        float* mo = maskout + (size_t)b * HW + (y0 + r0) * W + (x0 + tx);
        #pragma unroll
        for (int i = 0; i < 8; i++) {
            const float pooled = fmaxf(p[i], p[i + 3]);
            const float pcv = pos[(r0 + i + 5) * 81 + tx + 8];
            mo[i * W] = (pcv == pooled && pcv > 0.5f) ? 1.0f : 0.0f;
        }
    }
}

extern "C" void kernel_launch(void* const* d_in, const int* in_sizes, int n_in,
                              void* d_out, int out_size)
{
    const float* C = (const float*)d_in[0];
    const float* S = (const float*)d_in[1];
    float* out  = (float*)d_out;
    float* resp = out;                    // [0, 8*HW)   : conv_resp
    float* mask = out + (size_t)HW * 8;   // [8*HW,16*HW): mask as 0/1 float

    // Host-side function config: not an allocation, not a stream op ->
    // graph-capture safe; idempotent.
    cudaFuncSetAttribute(conv_kernel,
                         cudaFuncAttributeMaxDynamicSharedMemorySize,
                         CONV_SMEM_BYTES);

    dim3 gA(12, 12, 8);
    dim3 gB(12, 24, 8);
    conv_kernel<<<gA, 256, CONV_SMEM_BYTES>>>(C, S, resp);
    pool_kernel<<<gB, 256>>>(resp, mask);
}

// round 14
// speedup vs baseline: 1.0532x; 1.0532x over previous
#include <cuda_runtime.h>

#define W 768
#define H 768
#define HW 589824

// Dynamic shared memory layout for conv_kernel (bytes):
//   Pc    @ 0      : 129*64*4 = 33024   (inclusive column prefix of C)
//   Ps    @ 33024  : 64*129*4 = 33024   (inclusive row prefix of S)
//   segC4 @ 66048  : 16*16*16 = 4096    (per-segment C column sums, float4)
#define CONV_SMEM_BYTES 70144
#define PS_OFF   (33024 / 4)
#define SEG_OFF  (66048 / 16)

// ---------------------------------------------------------------------------
// Kernel A: multi-scale directional response via tile prefix sums.
// Construction identical to R9. Compute phase NEW: each thread stages the 81
// distinct Pc values it needs (16 rows x 16 offsets collapse to j=0..80) in
// registers with static indices -> Pc crossbar words drop 16/px -> 5.06/px
// and Pc LDS instructions 256 -> 81 per thread.
// launch_bounds(256,2): 128-reg budget so the 81-float stage stays resident.
// ---------------------------------------------------------------------------
__global__ __launch_bounds__(256, 2) void conv_kernel(
    const float* __restrict__ Cg, const float* __restrict__ Sg,
    float* __restrict__ out)
{
    extern __shared__ float smem[];
    float* Pc = smem;                          // [129 * 64]
    float* Ps = smem + PS_OFF;                 // [64 * 129]
    float4* segC4 = (float4*)smem + SEG_OFF;   // [16 * 16]

    const int tid = threadIdx.x;
    const int b  = blockIdx.z;
    const int x0 = blockIdx.x * 64;
    const int y0 = blockIdx.y * 64;
    const float* Cb = Cg + (size_t)b * HW;
    const float* Sb = Sg + (size_t)b * HW;

    const int q  = tid & 15;            // quad-column (cols q*4 .. q*4+3)
    const int sg = tid >> 4;            // 0..15, 8 C-rows each

    // ---- C halo load (rows y0-32 .. y0+95): within-segment prefix held in
    //      registers; only the segment sum hits smem before the sync.
    float4 cpre[8];
    {
        float4 s = make_float4(0.f, 0.f, 0.f, 0.f);
        if (blockIdx.y >= 1 && blockIdx.y <= 10) {       // interior rows
            const float* src = Cb + (y0 - 32 + sg * 8) * W + x0 + q * 4;
            #pragma unroll
            for (int jj = 0; jj < 8; jj++) {
                const float4 v = *(const float4*)(src + jj * W);
                s.x += v.x; s.y += v.y; s.z += v.z; s.w += v.w;
                cpre[jj] = s;
            }
        } else {
            #pragma unroll
            for (int jj = 0; jj < 8; jj++) {
                const int gy = y0 - 32 + sg * 8 + jj;
                float4 v = make_float4(0.f, 0.f, 0.f, 0.f);
                if (gy >= 0 && gy < H)
                    v = *(const float4*)(Cb + gy * W + x0 + q * 4);
                s.x += v.x; s.y += v.y; s.z += v.z; s.w += v.w;
                cpre[jj] = s;
            }
        }
        segC4[sg * 16 + q] = s;
    }

    // ---- S prefix: warp shuffle scan, one warp per row, 8 rows per warp.
    {
        const int l = tid & 31, wp = tid >> 5;
        const int gx0 = x0 - 32 + l * 4;                 // quad-aligned
        const bool intx = (blockIdx.x >= 1) & (blockIdx.x <= 10);
        const bool okx = intx | ((gx0 >= 0) & (gx0 < W)); // all-in or all-out
        #pragma unroll
        for (int rr = 0; rr < 8; rr++) {
            const int row = rr * 8 + wp;
            float4 v = make_float4(0.f, 0.f, 0.f, 0.f);
            if (okx) v = *(const float4*)(Sb + (y0 + row) * W + gx0);
            const float p0 = v.x, p1 = p0 + v.y, p2 = p1 + v.z, p3 = p2 + v.w;
            float t = p3;
            #pragma unroll
            for (int d = 1; d < 32; d <<= 1) {
                const float u = __shfl_up_sync(0xffffffffu, t, d);
                if (l >= d) t += u;
            }
            const float base = t - p3;                   // exclusive base
            float* pr = Ps + row * 129;
            if (l == 0) pr[0] = 0.0f;
            pr[1 + l * 4 + 0] = base + p0;
            pr[1 + l * 4 + 1] = base + p1;
            pr[1 + l * 4 + 2] = base + p2;
            pr[1 + l * 4 + 3] = base + p3;
        }
    }
    __syncthreads();

    // ---- exclusive scan of segC4 in place: 64 threads, conflict-free.
    if (tid < 64) {
        float* arr = (float*)segC4;
        float run = 0.0f;
        #pragma unroll
        for (int s2 = 0; s2 < 16; s2++) {
            const float v = arr[s2 * 64 + tid];
            arr[s2 * 64 + tid] = run;
            run += v;
        }
    }
    __syncthreads();

    // ---- C: add exclusive segment base (single LDS.128), single store pass
    {
        const float4 base = segC4[sg * 16 + q];
        float* dst = Pc + (sg * 8 + 1) * 64 + q * 4;
        #pragma unroll
        for (int jj = 0; jj < 8; jj++) {
            float4 p = cpre[jj];
            p.x += base.x; p.y += base.y; p.z += base.z; p.w += base.w;
            *(float4*)(dst + jj * 64) = p;
        }
        if (tid < 16)
            *(float4*)(Pc + tid * 4) = make_float4(0.f, 0.f, 0.f, 0.f);
    }
    __syncthreads();

    // ---- compute: thread = (col tx, 16 consecutive rows).
    // Stage the 81 distinct Pc values (rows tg*16 .. tg*16+80 of the prefix)
    // in registers; all later indices are compile-time constants.
    const int tx = tid & 63;
    const int tg = tid >> 6;
    const float* pc = Pc + (tg * 16) * 64 + tx;

    float pcv[81];
    #pragma unroll
    for (int j = 0; j < 81; j++) pcv[j] = pc[j * 64];

    const int XK[7] = {1, 4, 7, 10, 15, 25, 32};
    const float IW[7] = {0.5f, 0.125f, 1.0f / 14.0f, 0.05f,
                         1.0f / 30.0f, 0.02f, 1.0f / 64.0f};
    const int wi = tx + 32;
    float* ob = out + (size_t)b * HW + (y0 + tg * 16) * W + (x0 + tx);

    #pragma unroll
    for (int i = 0; i < 16; i++) {
        const float* psrow = Ps + (tg * 16 + i) * 129;
        const float base = pcv[i + 32] + pcv[i + 33]
                         + psrow[wi] + psrow[wi + 1];
        float r = -3.0e38f;
        #pragma unroll
        for (int k = 0; k < 7; k++) {
            const float t = base
                          - pcv[i + 32 - XK[k]]
                          - pcv[i + 33 + XK[k]]
                          - psrow[wi - XK[k]]
                          - psrow[wi + XK[k] + 1];
            r = fmaxf(r, t * IW[k]);
        }
        ob[i * W] = r;
    }
}

// ---------------------------------------------------------------------------
// Kernel B: pos = relu(resp); 11x11 max pool (separable in-place register
// max pyramid); mask = (pos==pooled && pos>0.5).
// Byte-identical to the R9 version (64x64 tile, 320 threads, measured
// 14.1us) — the R13 64x32/6-block redesign regressed and is reverted.
// ---------------------------------------------------------------------------
__global__ __launch_bounds__(320, 2) void pool_kernel(
    const float* __restrict__ resp, float* __restrict__ maskout)
{
    __shared__ float pos[74 * 81];
    __shared__ float hm[74 * 65];

    const int tid = threadIdx.x;
    const int b  = blockIdx.z;
    const int x0 = blockIdx.x * 64;
    const int y0 = blockIdx.y * 64;
    const float* rb = resp + (size_t)b * HW;

    {
        const int c4 = tid % 20;
        const int rg = tid / 20;
        const int gx0 = x0 - 8 + c4 * 4;
        const bool interior = (blockIdx.x >= 1) & (blockIdx.x <= 10) &
                              (blockIdx.y >= 1) & (blockIdx.y <= 10);
        if (interior) {
            const float* src = rb + (y0 - 5) * W + gx0;
            #pragma unroll
            for (int k = 0; k < 5; k++) {
                const int r = rg + k * 16;
                if (r < 74) {
                    const float4 v = *(const float4*)(src + r * W);
                    float* dst = pos + r * 81 + c4 * 4;
                    dst[0] = fmaxf(v.x, 0.f);
                    dst[1] = fmaxf(v.y, 0.f);
                    dst[2] = fmaxf(v.z, 0.f);
                    dst[3] = fmaxf(v.w, 0.f);
                }
            }
        } else {
            const bool okx = (gx0 >= 0) & (gx0 < W);
            #pragma unroll
            for (int k = 0; k < 5; k++) {
                const int r = rg + k * 16;
                if (r < 74) {
                    const int gy = y0 - 5 + r;
                    float4 v = make_float4(0.f, 0.f, 0.f, 0.f);
                    if (okx & (gy >= 0) & (gy < H))
                        v = *(const float4*)(rb + gy * W + gx0);
                    float* dst = pos + r * 81 + c4 * 4;
                    dst[0] = fmaxf(v.x, 0.f);
                    dst[1] = fmaxf(v.y, 0.f);
                    dst[2] = fmaxf(v.z, 0.f);
                    dst[3] = fmaxf(v.w, 0.f);
                }
            }
        }
    }
    __syncthreads();

    if (tid < 296) {
        const int seg = (tid >= 222) ? 3 : (tid >= 148) ? 2 : (tid >= 74) ? 1 : 0;
        const int r   = tid - seg * 74;
        const int c0  = seg * 16;
        const float* src = pos + r * 81 + c0 + 3;
        float p[26];
        #pragma unroll
        for (int i = 0; i < 26; i++) p[i] = src[i];
        #pragma unroll
        for (int i = 0; i < 25; i++) p[i] = fmaxf(p[i], p[i + 1]);
        #pragma unroll
        for (int i = 0; i < 23; i++) p[i] = fmaxf(p[i], p[i + 2]);
        #pragma unroll
        for (int i = 0; i < 19; i++) p[i] = fmaxf(p[i], p[i + 4]);
        float* hr = hm + r * 65 + c0;
        #pragma unroll
        for (int i = 0; i < 16; i++) hr[i] = fmaxf(p[i], p[i + 3]);
    }
    __syncthreads();

    if (tid < 256) {
        const int tx = tid & 63;
        const int r0 = (tid >> 6) * 16;
        float p[26];
        #pragma unroll
        for (int i = 0; i < 26; i++) p[i] = hm[(r0 + i) * 65 + tx];
        #pragma unroll
        for (int i = 0; i < 25; i++) p[i] = fmaxf(p[i], p[i + 1]);
        #pragma unroll
        for (int i = 0; i < 23; i++) p[i] = fmaxf(p[i], p[i + 2]);
        #pragma unroll
        for (int i = 0; i < 19; i++) p[i] = fmaxf(p[i], p[i + 4]);
        float* mo = maskout + (size_t)b * HW + (y0 + r0) * W + (x0 + tx);
        #pragma unroll
        for (int i = 0; i < 16; i++) {
            const float pooled = fmaxf(p[i], p[i + 3]);
            const float pcv = pos[(r0 + i + 5) * 81 + tx + 8];
            mo[i * W] = (pcv == pooled && pcv > 0.5f) ? 1.0f : 0.0f;
        }
    }
}

extern "C" void kernel_launch(void* const* d_in, const int* in_sizes, int n_in,
                              void* d_out, int out_size)
{
    const float* C = (const float*)d_in[0];
    const float* S = (const float*)d_in[1];
    float* out  = (float*)d_out;
    float* resp = out;                    // [0, 8*HW)   : conv_resp
    float* mask = out + (size_t)HW * 8;   // [8*HW,16*HW): mask as 0/1 float

    // Host-side function config: not an allocation, not a stream op ->
    // graph-capture safe; idempotent.
    cudaFuncSetAttribute(conv_kernel,
                         cudaFuncAttributeMaxDynamicSharedMemorySize,
                         CONV_SMEM_BYTES);

    dim3 gA(12, 12, 8);
    dim3 gB(12, 12, 8);
    conv_kernel<<<gA, 256, CONV_SMEM_BYTES>>>(C, S, resp);
    pool_kernel<<<gB, 320>>>(resp, mask);
}